// round 8
// baseline (speedup 1.0000x reference)
#include <cuda_runtime.h>
#include <cuda_bf16.h>
#include <math_constants.h>

#define B_  8
#define SQ_ 128
#define SK_ 1024
#define U_  256

// Scratch for projected q and k (allocation-free rule: __device__ globals)
__device__ float g_q[B_ * SQ_ * U_];   // 1 MB
__device__ float g_k[B_ * SK_ * U_];   // 8 MB

__device__ __forceinline__ float tanha(float x) {
    float y;
    asm("tanh.approx.f32 %0, %1;" : "=f"(y) : "f"(x));
    return y;
}

// ---------------------------------------------------------------------------
// tf32 helpers: 3-term split GEMM gives ~fp32 accuracy on tensor cores.
// ---------------------------------------------------------------------------
__device__ __forceinline__ void tf32_split(float x, float& hi, float& lo) {
    unsigned u;
    asm("cvt.rna.tf32.f32 %0, %1;" : "=r"(u) : "f"(x));
    hi = __uint_as_float(u);
    float l = x - hi;
    unsigned ul;
    asm("cvt.rna.tf32.f32 %0, %1;" : "=r"(ul) : "f"(l));
    lo = __uint_as_float(ul);
}

__device__ __forceinline__ void mma_tf32(float& d0, float& d1, float& d2, float& d3,
                                         unsigned a0, unsigned a1, unsigned a2, unsigned a3,
                                         unsigned b0, unsigned b1) {
    asm("mma.sync.aligned.m16n8k8.row.col.f32.tf32.tf32.f32 "
        "{%0,%1,%2,%3}, {%4,%5,%6,%7}, {%8,%9}, {%0,%1,%2,%3};"
        : "+f"(d0), "+f"(d1), "+f"(d2), "+f"(d3)
        : "r"(a0), "r"(a1), "r"(a2), "r"(a3), "r"(b0), "r"(b1));
}

// ---------------------------------------------------------------------------
// Tensor-core SGEMM, tf32 3-term split: C = A @ B (both row-major, f32).
// CTA tile: (32*IM) x 64, K-chunk 32. 8 warps as 2(m) x 4(n). Batched via z.
// ---------------------------------------------------------------------------
template <int IM>
__global__ void gemm_tc(const float* __restrict__ A, const float* __restrict__ Bm,
                        float* __restrict__ C, int M, int N, int K,
                        long long sA, long long sB, long long sC) {
    constexpr int TM = 32 * IM;
    A  += (long long)blockIdx.z * sA;
    Bm += (long long)blockIdx.z * sB;
    C  += (long long)blockIdx.z * sC;

    __shared__ float Ah[TM][36], Al[TM][36];
    __shared__ float Bh[32][72], Bl[32][72];

    const int tid  = threadIdx.x;
    const int lane = tid & 31;
    const int warp = tid >> 5;
    const int wm   = warp >> 2;
    const int wn   = warp & 3;
    const int gid  = lane >> 2;
    const int tig  = lane & 3;
    const int m_base = wm * (16 * IM);
    const int n_base = wn * 16;

    const int m0 = blockIdx.y * TM;
    const int n0 = blockIdx.x * 64;

    float acc[IM][2][4];
#pragma unroll
    for (int im = 0; im < IM; im++)
#pragma unroll
        for (int in = 0; in < 2; in++)
#pragma unroll
            for (int c = 0; c < 4; c++) acc[im][in][c] = 0.0f;

    for (int k0 = 0; k0 < K; k0 += 32) {
#pragma unroll
        for (int it = 0; it < (TM * 8) / 256; it++) {
            int idx = tid + it * 256;
            int r = idx >> 3;
            int c = (idx & 7) << 2;
            float4 v = *(const float4*)&A[(long long)(m0 + r) * K + k0 + c];
            float h0, l0, h1, l1, h2, l2, h3, l3;
            tf32_split(v.x, h0, l0); tf32_split(v.y, h1, l1);
            tf32_split(v.z, h2, l2); tf32_split(v.w, h3, l3);
            *(float4*)&Ah[r][c] = make_float4(h0, h1, h2, h3);
            *(float4*)&Al[r][c] = make_float4(l0, l1, l2, l3);
        }
#pragma unroll
        for (int it = 0; it < 2; it++) {
            int idx = tid + it * 256;
            int r = idx >> 4;
            int c = (idx & 15) << 2;
            float4 v = *(const float4*)&Bm[(long long)(k0 + r) * N + n0 + c];
            float h0, l0, h1, l1, h2, l2, h3, l3;
            tf32_split(v.x, h0, l0); tf32_split(v.y, h1, l1);
            tf32_split(v.z, h2, l2); tf32_split(v.w, h3, l3);
            *(float4*)&Bh[r][c] = make_float4(h0, h1, h2, h3);
            *(float4*)&Bl[r][c] = make_float4(l0, l1, l2, l3);
        }
        __syncthreads();

#pragma unroll
        for (int kk = 0; kk < 4; kk++) {
            const int kb = kk * 8;
            unsigned ah[IM][4], al[IM][4];
#pragma unroll
            for (int im = 0; im < IM; im++) {
                int r0 = m_base + 16 * im + gid;
                ah[im][0] = __float_as_uint(Ah[r0    ][kb + tig    ]);
                ah[im][1] = __float_as_uint(Ah[r0 + 8][kb + tig    ]);
                ah[im][2] = __float_as_uint(Ah[r0    ][kb + tig + 4]);
                ah[im][3] = __float_as_uint(Ah[r0 + 8][kb + tig + 4]);
                al[im][0] = __float_as_uint(Al[r0    ][kb + tig    ]);
                al[im][1] = __float_as_uint(Al[r0 + 8][kb + tig    ]);
                al[im][2] = __float_as_uint(Al[r0    ][kb + tig + 4]);
                al[im][3] = __float_as_uint(Al[r0 + 8][kb + tig + 4]);
            }
            unsigned bh[2][2], bl[2][2];
#pragma unroll
            for (int in = 0; in < 2; in++) {
                int c0 = n_base + 8 * in + gid;
                bh[in][0] = __float_as_uint(Bh[kb + tig    ][c0]);
                bh[in][1] = __float_as_uint(Bh[kb + tig + 4][c0]);
                bl[in][0] = __float_as_uint(Bl[kb + tig    ][c0]);
                bl[in][1] = __float_as_uint(Bl[kb + tig + 4][c0]);
            }
#pragma unroll
            for (int im = 0; im < IM; im++)
#pragma unroll
                for (int in = 0; in < 2; in++) {
                    float* d = acc[im][in];
                    mma_tf32(d[0], d[1], d[2], d[3],
                             ah[im][0], ah[im][1], ah[im][2], ah[im][3],
                             bh[in][0], bh[in][1]);
                    mma_tf32(d[0], d[1], d[2], d[3],
                             ah[im][0], ah[im][1], ah[im][2], ah[im][3],
                             bl[in][0], bl[in][1]);
                    mma_tf32(d[0], d[1], d[2], d[3],
                             al[im][0], al[im][1], al[im][2], al[im][3],
                             bh[in][0], bh[in][1]);
                }
        }
        __syncthreads();
    }

#pragma unroll
    for (int im = 0; im < IM; im++) {
#pragma unroll
        for (int in = 0; in < 2; in++) {
            int row = m0 + m_base + 16 * im + gid;
            int col = n0 + n_base + 8 * in + 2 * tig;
            float* d = acc[im][in];
            *(float2*)&C[(long long)row * N + col]       = make_float2(d[0], d[1]);
            *(float2*)&C[(long long)(row + 8) * N + col] = make_float2(d[2], d[3]);
        }
    }
}

// ---------------------------------------------------------------------------
// Scores v4: hybrid tanh. Half the u-elements use HW tanh.approx.f32 (MUFU),
// half use a 128-segment piecewise-linear smem table (FMA/ALU/LDS pipes).
// This breaks the MUFU.TANH rt16 throughput wall.
// score[b,i,j] = sum_u tanh(q[b,i,u] + k[b,j,u]) * wv[u]
// ---------------------------------------------------------------------------
#define TQ 16
#define TAB_N   128
#define TAB_H   0.03515625f            // 4.5 / 128
#define TAB_I8  227.55556f             // 8 / TAB_H (byte-index scale for float2)

__device__ __forceinline__ float tanh_tab(float s, const float2* __restrict__ tab) {
    float as = fabsf(s);
    float t8 = fminf(as * TAB_I8, 1016.0f);   // clamp to entry 127 (byte off 1016)
    int i8 = ((int)t8) & ~7;                  // float2-aligned byte offset
    float2 ab = *(const float2*)((const char*)tab + i8);
    float y = fmaf(ab.x, as, ab.y);           // y in [0, 1]
    return __uint_as_float((__float_as_uint(y) & 0x7fffffffu) |
                           (__float_as_uint(s) & 0x80000000u));
}

__global__ void scores_kernel(const float* __restrict__ wv, float* __restrict__ attn) {
    const int b  = blockIdx.z;
    const int ib = blockIdx.y;
    const int tid = threadIdx.x;
    const int j  = blockIdx.x * 256 + tid;

    __shared__ float qs[TQ][U_];       // 16 KB
    __shared__ float wvs[U_];
    __shared__ float2 tab[TAB_N];      // 1 KB PWL tanh table

    // Build table (once per CTA; 128 threads)
    if (tid < TAB_N) {
        float x0 = tid * TAB_H;
        float t0 = tanhf(x0);
        float t1 = tanhf(x0 + TAB_H);
        float a = (t1 - t0) * (1.0f / TAB_H);
        float bb = t0 - a * x0;
        if (tid == TAB_N - 1) { a = 0.0f; bb = 0.99987f; }  // clamp entry
        tab[tid] = make_float2(a, bb);
    }

    const float* qbase = g_q + ((long long)(b * SQ_ + ib * TQ)) * U_;
#pragma unroll
    for (int l = 0; l < 4; l++) {
        int idx = tid + l * 256;
        int row = idx >> 6;
        int col = (idx & 63) << 2;
        *(float4*)&qs[row][col] = *(const float4*)&qbase[(long long)row * U_ + col];
    }
    if (tid < 64) *(float4*)&wvs[tid << 2] = *(const float4*)&wv[tid << 2];
    __syncthreads();

    const float* kp = g_k + ((long long)(b * SK_) + j) * U_;

    float acc[TQ];
#pragma unroll
    for (int i = 0; i < TQ; i++) acc[i] = 0.0f;

    float4 ka = *(const float4*)&kp[0];
    float4 kb = *(const float4*)&kp[4];

    for (int uc = 0; uc < U_; uc += 8) {            // no outer unroll: keep I$ resident
        int un = (uc + 8 < U_) ? uc + 8 : uc;       // clamped tail prefetch
        float4 kna = *(const float4*)&kp[un];
        float4 knb = *(const float4*)&kp[un + 4];
        float4 w0 = *(const float4*)&wvs[uc];
        float4 w1 = *(const float4*)&wvs[uc + 4];
#pragma unroll
        for (int i = 0; i < TQ; i++) {
            float4 q0 = *(const float4*)&qs[i][uc];        // broadcast LDS
            float4 q1 = *(const float4*)&qs[i][uc + 4];    // broadcast LDS
            float s;
            // MUFU path (x, y) + table path (z, w) — balanced across pipes
            s  = tanha(q0.x + ka.x) * w0.x;
            s += tanha(q0.y + ka.y) * w0.y;
            s += tanh_tab(q0.z + ka.z, tab) * w0.z;
            s += tanh_tab(q0.w + ka.w, tab) * w0.w;
            s += tanha(q1.x + kb.x) * w1.x;
            s += tanha(q1.y + kb.y) * w1.y;
            s += tanh_tab(q1.z + kb.z, tab) * w1.z;
            s += tanh_tab(q1.w + kb.w, tab) * w1.w;
            acc[i] += s;
        }
        ka = kna;
        kb = knb;
    }

    long long base = ((long long)(b * SQ_ + ib * TQ)) * SK_ + j;
#pragma unroll
    for (int i = 0; i < TQ; i++) attn[base + (long long)i * SK_] = acc[i];
}

// ---------------------------------------------------------------------------
// Row softmax over SK=1024, in place. One CTA (256 threads) per (b,i) row.
// ---------------------------------------------------------------------------
__global__ void softmax_kernel(float* __restrict__ attn) {
    float* p = attn + (long long)blockIdx.x * SK_;
    const int tid = threadIdx.x;
    __shared__ float red[8];

    float4 x = *(const float4*)&p[tid << 2];
    float m = fmaxf(fmaxf(x.x, x.y), fmaxf(x.z, x.w));
#pragma unroll
    for (int o = 16; o; o >>= 1) m = fmaxf(m, __shfl_xor_sync(0xffffffffu, m, o));
    if ((tid & 31) == 0) red[tid >> 5] = m;
    __syncthreads();
    float M = red[0];
#pragma unroll
    for (int w = 1; w < 8; w++) M = fmaxf(M, red[w]);

    float4 e;
    e.x = __expf(x.x - M);
    e.y = __expf(x.y - M);
    e.z = __expf(x.z - M);
    e.w = __expf(x.w - M);
    float s = (e.x + e.y) + (e.z + e.w);
#pragma unroll
    for (int o = 16; o; o >>= 1) s += __shfl_xor_sync(0xffffffffu, s, o);
    __syncthreads();
    if ((tid & 31) == 0) red[tid >> 5] = s;
    __syncthreads();
    float S = 0.f;
#pragma unroll
    for (int w = 0; w < 8; w++) S += red[w];
    float inv = 1.0f / S;
    e.x *= inv; e.y *= inv; e.z *= inv; e.w *= inv;
    *(float4*)&p[tid << 2] = e;
}

// ---------------------------------------------------------------------------
extern "C" void kernel_launch(void* const* d_in, const int* in_sizes, int n_in,
                              void* d_out, int out_size) {
    const float* query = (const float*)d_in[0];
    const float* key   = (const float*)d_in[1];
    const float* value = (const float*)d_in[2];
    const float* Wq    = (const float*)d_in[3];
    const float* Wk    = (const float*)d_in[4];
    const float* wv    = (const float*)d_in[5];

    float* out  = (float*)d_out;
    float* ctx  = out;                            // [B, SQ, U]
    float* attn = out + (long long)B_ * SQ_ * U_; // [B, SQ, SK]

    void* pq = nullptr; void* pk = nullptr;
    cudaGetSymbolAddress(&pq, g_q);
    cudaGetSymbolAddress(&pk, g_k);
    float* dq = (float*)pq;
    float* dk = (float*)pk;

    // 1) Projections on tensor cores (tf32 3-term split)
    gemm_tc<2><<<dim3(U_ / 64, (B_ * SQ_) / 64, 1), 256>>>(
        query, Wq, dq, B_ * SQ_, U_, U_, 0, 0, 0);
    gemm_tc<2><<<dim3(U_ / 64, (B_ * SK_) / 64, 1), 256>>>(
        key, Wk, dk, B_ * SK_, U_, U_, 0, 0, 0);

    // 2) Raw scores (hybrid tanh) into the attention-weights output region
    scores_kernel<<<dim3(SK_ / 256, SQ_ / TQ, B_), 256>>>(wv, attn);

    // 3) Softmax in place
    softmax_kernel<<<B_ * SQ_, 256>>>(attn);

    // 4) context = attn @ value (batched, M=128 N=256 K=1024)
    gemm_tc<1><<<dim3(U_ / 64, SQ_ / 32, B_), 256>>>(
        attn, value, ctx, SQ_, U_, SK_,
        (long long)SQ_ * SK_, (long long)SK_ * U_, (long long)SQ_ * U_);
}

// round 9
// speedup vs baseline: 1.0839x; 1.0839x over previous
#include <cuda_runtime.h>
#include <cuda_bf16.h>
#include <math_constants.h>

#define B_  8
#define SQ_ 128
#define SK_ 1024
#define U_  256

// Scratch for tanh(projected q) and tanh(projected k)
__device__ float g_q[B_ * SQ_ * U_];   // 1 MB
__device__ float g_k[B_ * SK_ * U_];   // 8 MB

__device__ __forceinline__ float tanha(float x) {
    float y;
    asm("tanh.approx.f32 %0, %1;" : "=f"(y) : "f"(x));
    return y;
}

__device__ __forceinline__ float rcpa(float x) {
    float y;
    asm("rcp.approx.f32 %0, %1;" : "=f"(y) : "f"(x));
    return y;
}

// ---------------------------------------------------------------------------
// tf32 helpers: 3-term split GEMM gives ~fp32 accuracy on tensor cores.
// ---------------------------------------------------------------------------
__device__ __forceinline__ void tf32_split(float x, float& hi, float& lo) {
    unsigned u;
    asm("cvt.rna.tf32.f32 %0, %1;" : "=r"(u) : "f"(x));
    hi = __uint_as_float(u);
    float l = x - hi;
    unsigned ul;
    asm("cvt.rna.tf32.f32 %0, %1;" : "=r"(ul) : "f"(l));
    lo = __uint_as_float(ul);
}

__device__ __forceinline__ void mma_tf32(float& d0, float& d1, float& d2, float& d3,
                                         unsigned a0, unsigned a1, unsigned a2, unsigned a3,
                                         unsigned b0, unsigned b1) {
    asm("mma.sync.aligned.m16n8k8.row.col.f32.tf32.tf32.f32 "
        "{%0,%1,%2,%3}, {%4,%5,%6,%7}, {%8,%9}, {%0,%1,%2,%3};"
        : "+f"(d0), "+f"(d1), "+f"(d2), "+f"(d3)
        : "r"(a0), "r"(a1), "r"(a2), "r"(a3), "r"(b0), "r"(b1));
}

// ---------------------------------------------------------------------------
// Tensor-core SGEMM, tf32 3-term split: C = A @ B (both row-major, f32).
// CTA tile: (32*IM) x 64, K-chunk 32. 8 warps as 2(m) x 4(n). Batched via z.
// TANH: apply tanh.approx to outputs in the epilogue (for q/k projections,
// feeding the tanh addition-formula scores kernel).
// ---------------------------------------------------------------------------
template <int IM, bool TANH>
__global__ void gemm_tc(const float* __restrict__ A, const float* __restrict__ Bm,
                        float* __restrict__ C, int M, int N, int K,
                        long long sA, long long sB, long long sC) {
    constexpr int TM = 32 * IM;
    A  += (long long)blockIdx.z * sA;
    Bm += (long long)blockIdx.z * sB;
    C  += (long long)blockIdx.z * sC;

    __shared__ float Ah[TM][36], Al[TM][36];
    __shared__ float Bh[32][72], Bl[32][72];

    const int tid  = threadIdx.x;
    const int lane = tid & 31;
    const int warp = tid >> 5;
    const int wm   = warp >> 2;
    const int wn   = warp & 3;
    const int gid  = lane >> 2;
    const int tig  = lane & 3;
    const int m_base = wm * (16 * IM);
    const int n_base = wn * 16;

    const int m0 = blockIdx.y * TM;
    const int n0 = blockIdx.x * 64;

    float acc[IM][2][4];
#pragma unroll
    for (int im = 0; im < IM; im++)
#pragma unroll
        for (int in = 0; in < 2; in++)
#pragma unroll
            for (int c = 0; c < 4; c++) acc[im][in][c] = 0.0f;

    for (int k0 = 0; k0 < K; k0 += 32) {
#pragma unroll
        for (int it = 0; it < (TM * 8) / 256; it++) {
            int idx = tid + it * 256;
            int r = idx >> 3;
            int c = (idx & 7) << 2;
            float4 v = *(const float4*)&A[(long long)(m0 + r) * K + k0 + c];
            float h0, l0, h1, l1, h2, l2, h3, l3;
            tf32_split(v.x, h0, l0); tf32_split(v.y, h1, l1);
            tf32_split(v.z, h2, l2); tf32_split(v.w, h3, l3);
            *(float4*)&Ah[r][c] = make_float4(h0, h1, h2, h3);
            *(float4*)&Al[r][c] = make_float4(l0, l1, l2, l3);
        }
#pragma unroll
        for (int it = 0; it < 2; it++) {
            int idx = tid + it * 256;
            int r = idx >> 4;
            int c = (idx & 15) << 2;
            float4 v = *(const float4*)&Bm[(long long)(k0 + r) * N + n0 + c];
            float h0, l0, h1, l1, h2, l2, h3, l3;
            tf32_split(v.x, h0, l0); tf32_split(v.y, h1, l1);
            tf32_split(v.z, h2, l2); tf32_split(v.w, h3, l3);
            *(float4*)&Bh[r][c] = make_float4(h0, h1, h2, h3);
            *(float4*)&Bl[r][c] = make_float4(l0, l1, l2, l3);
        }
        __syncthreads();

#pragma unroll
        for (int kk = 0; kk < 4; kk++) {
            const int kb = kk * 8;
            unsigned ah[IM][4], al[IM][4];
#pragma unroll
            for (int im = 0; im < IM; im++) {
                int r0 = m_base + 16 * im + gid;
                ah[im][0] = __float_as_uint(Ah[r0    ][kb + tig    ]);
                ah[im][1] = __float_as_uint(Ah[r0 + 8][kb + tig    ]);
                ah[im][2] = __float_as_uint(Ah[r0    ][kb + tig + 4]);
                ah[im][3] = __float_as_uint(Ah[r0 + 8][kb + tig + 4]);
                al[im][0] = __float_as_uint(Al[r0    ][kb + tig    ]);
                al[im][1] = __float_as_uint(Al[r0 + 8][kb + tig    ]);
                al[im][2] = __float_as_uint(Al[r0    ][kb + tig + 4]);
                al[im][3] = __float_as_uint(Al[r0 + 8][kb + tig + 4]);
            }
            unsigned bh[2][2], bl[2][2];
#pragma unroll
            for (int in = 0; in < 2; in++) {
                int c0 = n_base + 8 * in + gid;
                bh[in][0] = __float_as_uint(Bh[kb + tig    ][c0]);
                bh[in][1] = __float_as_uint(Bh[kb + tig + 4][c0]);
                bl[in][0] = __float_as_uint(Bl[kb + tig    ][c0]);
                bl[in][1] = __float_as_uint(Bl[kb + tig + 4][c0]);
            }
#pragma unroll
            for (int im = 0; im < IM; im++)
#pragma unroll
                for (int in = 0; in < 2; in++) {
                    float* d = acc[im][in];
                    mma_tf32(d[0], d[1], d[2], d[3],
                             ah[im][0], ah[im][1], ah[im][2], ah[im][3],
                             bh[in][0], bh[in][1]);
                    mma_tf32(d[0], d[1], d[2], d[3],
                             ah[im][0], ah[im][1], ah[im][2], ah[im][3],
                             bl[in][0], bl[in][1]);
                    mma_tf32(d[0], d[1], d[2], d[3],
                             al[im][0], al[im][1], al[im][2], al[im][3],
                             bh[in][0], bh[in][1]);
                }
        }
        __syncthreads();
    }

#pragma unroll
    for (int im = 0; im < IM; im++) {
#pragma unroll
        for (int in = 0; in < 2; in++) {
            int row = m0 + m_base + 16 * im + gid;
            int col = n0 + n_base + 8 * in + 2 * tig;
            float* d = acc[im][in];
            if (TANH) {
#pragma unroll
                for (int c = 0; c < 4; c++) d[c] = tanha(d[c]);
            }
            *(float2*)&C[(long long)row * N + col]       = make_float2(d[0], d[1]);
            *(float2*)&C[(long long)(row + 8) * N + col] = make_float2(d[2], d[3]);
        }
    }
}

// ---------------------------------------------------------------------------
// Scores v5 (tanh addition formula):
//   tanh(q+k) = (tq + tk) / (1 + tq*tk),  tq/tk precomputed in GEMM epilogue.
// Per element: FADD + FFMA + RCP(rt8 MUFU) + FMUL + FFMA — MUFU load halved
// vs direct tanh (rt16), FMA pipe picks up the rest. Balanced ~113k cyc/SM.
// score[b,i,j] = sum_u tanh(q[b,i,u] + k[b,j,u]) * wv[u]
// ---------------------------------------------------------------------------
#define TQ 16

__global__ void scores_kernel(const float* __restrict__ wv, float* __restrict__ attn) {
    const int b  = blockIdx.z;
    const int ib = blockIdx.y;
    const int tid = threadIdx.x;
    const int j  = blockIdx.x * 256 + tid;

    __shared__ float qs[TQ][U_];   // tanh(q) tile, 16 KB
    __shared__ float wvs[U_];

    const float* qbase = g_q + ((long long)(b * SQ_ + ib * TQ)) * U_;
#pragma unroll
    for (int l = 0; l < 4; l++) {
        int idx = tid + l * 256;
        int row = idx >> 6;
        int col = (idx & 63) << 2;
        *(float4*)&qs[row][col] = *(const float4*)&qbase[(long long)row * U_ + col];
    }
    if (tid < 64) *(float4*)&wvs[tid << 2] = *(const float4*)&wv[tid << 2];
    __syncthreads();

    const float* kp = g_k + ((long long)(b * SK_) + j) * U_;

    float acc[TQ];
#pragma unroll
    for (int i = 0; i < TQ; i++) acc[i] = 0.0f;

    float4 ka = *(const float4*)&kp[0];
    float4 kb = *(const float4*)&kp[4];

    for (int uc = 0; uc < U_; uc += 8) {
        int un = (uc + 8 < U_) ? uc + 8 : uc;   // clamped tail prefetch
        float4 kna = *(const float4*)&kp[un];
        float4 knb = *(const float4*)&kp[un + 4];
        float4 w0 = *(const float4*)&wvs[uc];
        float4 w1 = *(const float4*)&wvs[uc + 4];
#pragma unroll
        for (int i = 0; i < TQ; i++) {
            float4 q0 = *(const float4*)&qs[i][uc];        // broadcast LDS (tq)
            float4 q1 = *(const float4*)&qs[i][uc + 4];
            float a = acc[i];
            {
                float nm = q0.x + ka.x;
                float r  = rcpa(fmaf(q0.x, ka.x, 1.0f));
                a = fmaf(nm * r, w0.x, a);
            }
            {
                float nm = q0.y + ka.y;
                float r  = rcpa(fmaf(q0.y, ka.y, 1.0f));
                a = fmaf(nm * r, w0.y, a);
            }
            {
                float nm = q0.z + ka.z;
                float r  = rcpa(fmaf(q0.z, ka.z, 1.0f));
                a = fmaf(nm * r, w0.z, a);
            }
            {
                float nm = q0.w + ka.w;
                float r  = rcpa(fmaf(q0.w, ka.w, 1.0f));
                a = fmaf(nm * r, w0.w, a);
            }
            {
                float nm = q1.x + kb.x;
                float r  = rcpa(fmaf(q1.x, kb.x, 1.0f));
                a = fmaf(nm * r, w1.x, a);
            }
            {
                float nm = q1.y + kb.y;
                float r  = rcpa(fmaf(q1.y, kb.y, 1.0f));
                a = fmaf(nm * r, w1.y, a);
            }
            {
                float nm = q1.z + kb.z;
                float r  = rcpa(fmaf(q1.z, kb.z, 1.0f));
                a = fmaf(nm * r, w1.z, a);
            }
            {
                float nm = q1.w + kb.w;
                float r  = rcpa(fmaf(q1.w, kb.w, 1.0f));
                a = fmaf(nm * r, w1.w, a);
            }
            acc[i] = a;
        }
        ka = kna;
        kb = knb;
    }

    long long base = ((long long)(b * SQ_ + ib * TQ)) * SK_ + j;
#pragma unroll
    for (int i = 0; i < TQ; i++) attn[base + (long long)i * SK_] = acc[i];
}

// ---------------------------------------------------------------------------
// Row softmax over SK=1024, in place. One CTA (256 threads) per (b,i) row.
// ---------------------------------------------------------------------------
__global__ void softmax_kernel(float* __restrict__ attn) {
    float* p = attn + (long long)blockIdx.x * SK_;
    const int tid = threadIdx.x;
    __shared__ float red[8];

    float4 x = *(const float4*)&p[tid << 2];
    float m = fmaxf(fmaxf(x.x, x.y), fmaxf(x.z, x.w));
#pragma unroll
    for (int o = 16; o; o >>= 1) m = fmaxf(m, __shfl_xor_sync(0xffffffffu, m, o));
    if ((tid & 31) == 0) red[tid >> 5] = m;
    __syncthreads();
    float M = red[0];
#pragma unroll
    for (int w = 1; w < 8; w++) M = fmaxf(M, red[w]);

    float4 e;
    e.x = __expf(x.x - M);
    e.y = __expf(x.y - M);
    e.z = __expf(x.z - M);
    e.w = __expf(x.w - M);
    float s = (e.x + e.y) + (e.z + e.w);
#pragma unroll
    for (int o = 16; o; o >>= 1) s += __shfl_xor_sync(0xffffffffu, s, o);
    __syncthreads();
    if ((tid & 31) == 0) red[tid >> 5] = s;
    __syncthreads();
    float S = 0.f;
#pragma unroll
    for (int w = 0; w < 8; w++) S += red[w];
    float inv = 1.0f / S;
    e.x *= inv; e.y *= inv; e.z *= inv; e.w *= inv;
    *(float4*)&p[tid << 2] = e;
}

// ---------------------------------------------------------------------------
extern "C" void kernel_launch(void* const* d_in, const int* in_sizes, int n_in,
                              void* d_out, int out_size) {
    const float* query = (const float*)d_in[0];
    const float* key   = (const float*)d_in[1];
    const float* value = (const float*)d_in[2];
    const float* Wq    = (const float*)d_in[3];
    const float* Wk    = (const float*)d_in[4];
    const float* wv    = (const float*)d_in[5];

    float* out  = (float*)d_out;
    float* ctx  = out;                            // [B, SQ, U]
    float* attn = out + (long long)B_ * SQ_ * U_; // [B, SQ, SK]

    void* pq = nullptr; void* pk = nullptr;
    cudaGetSymbolAddress(&pq, g_q);
    cudaGetSymbolAddress(&pk, g_k);
    float* dq = (float*)pq;
    float* dk = (float*)pk;

    // 1) Projections on tensor cores, tanh fused into epilogue:
    //    g_q = tanh(query @ Wq),  g_k = tanh(key @ Wk)
    gemm_tc<2, true><<<dim3(U_ / 64, (B_ * SQ_) / 64, 1), 256>>>(
        query, Wq, dq, B_ * SQ_, U_, U_, 0, 0, 0);
    gemm_tc<2, true><<<dim3(U_ / 64, (B_ * SK_) / 64, 1), 256>>>(
        key, Wk, dk, B_ * SK_, U_, U_, 0, 0, 0);

    // 2) Raw scores via tanh addition formula
    scores_kernel<<<dim3(SK_ / 256, SQ_ / TQ, B_), 256>>>(wv, attn);

    // 3) Softmax in place
    softmax_kernel<<<B_ * SQ_, 256>>>(attn);

    // 4) context = attn @ value (batched, M=128 N=256 K=1024)
    gemm_tc<1, false><<<dim3(U_ / 64, SQ_ / 32, B_), 256>>>(
        attn, value, ctx, SQ_, U_, SK_,
        (long long)SQ_ * SK_, (long long)SK_ * U_, (long long)SQ_ * U_);
}

// round 10
// speedup vs baseline: 1.6339x; 1.5074x over previous
#include <cuda_runtime.h>
#include <cuda_bf16.h>
#include <math_constants.h>

#define B_  8
#define SQ_ 128
#define SK_ 1024
#define U_  256

// Scratch for projected q and k (allocation-free rule: __device__ globals)
__device__ float g_q[B_ * SQ_ * U_];   // 1 MB
__device__ float g_k[B_ * SK_ * U_];   // 8 MB

__device__ __forceinline__ float tanha(float x) {
    float y;
    asm("tanh.approx.f32 %0, %1;" : "=f"(y) : "f"(x));
    return y;
}

__device__ __forceinline__ unsigned smem_u32(const void* p) {
    return (unsigned)__cvta_generic_to_shared(p);
}

// ---------------------------------------------------------------------------
// bf16 3-term split GEMM helpers
// ---------------------------------------------------------------------------
__device__ __forceinline__ void split_store8(float4 v,
                                             __nv_bfloat16* ph, __nv_bfloat16* pl) {
    __nv_bfloat162 h01 = __floats2bfloat162_rn(v.x, v.y);
    __nv_bfloat162 h23 = __floats2bfloat162_rn(v.z, v.w);
    __nv_bfloat162 l01 = __floats2bfloat162_rn(v.x - __bfloat162float(h01.x),
                                               v.y - __bfloat162float(h01.y));
    __nv_bfloat162 l23 = __floats2bfloat162_rn(v.z - __bfloat162float(h23.x),
                                               v.w - __bfloat162float(h23.y));
    *reinterpret_cast<__nv_bfloat162*>(ph)     = h01;
    *reinterpret_cast<__nv_bfloat162*>(ph + 2) = h23;
    *reinterpret_cast<__nv_bfloat162*>(pl)     = l01;
    *reinterpret_cast<__nv_bfloat162*>(pl + 2) = l23;
}

__device__ __forceinline__ void ldsm_x4(unsigned r[4], unsigned addr) {
    asm volatile("ldmatrix.sync.aligned.m8n8.x4.shared.b16 {%0,%1,%2,%3}, [%4];"
        : "=r"(r[0]), "=r"(r[1]), "=r"(r[2]), "=r"(r[3]) : "r"(addr));
}

__device__ __forceinline__ void ldsm_x4_t(unsigned r[4], unsigned addr) {
    asm volatile("ldmatrix.sync.aligned.m8n8.x4.trans.shared.b16 {%0,%1,%2,%3}, [%4];"
        : "=r"(r[0]), "=r"(r[1]), "=r"(r[2]), "=r"(r[3]) : "r"(addr));
}

__device__ __forceinline__ void mma_bf16(float* d, const unsigned a[4],
                                         unsigned b0, unsigned b1) {
    asm volatile("mma.sync.aligned.m16n8k16.row.col.f32.bf16.bf16.f32 "
        "{%0,%1,%2,%3}, {%4,%5,%6,%7}, {%8,%9}, {%0,%1,%2,%3};"
        : "+f"(d[0]), "+f"(d[1]), "+f"(d[2]), "+f"(d[3])
        : "r"(a[0]), "r"(a[1]), "r"(a[2]), "r"(a[3]), "r"(b0), "r"(b1));
}

// ---------------------------------------------------------------------------
// Tensor-core SGEMM, bf16 3-term split: C = A @ B (row-major f32 in/out).
// CTA tile: (32*IM) x 64, K-chunk 32 (2 mma k16 steps). 8 warps 2(m) x 4(n).
// Fragments via ldmatrix (A natural, B trans). Batched via blockIdx.z.
// ---------------------------------------------------------------------------
template <int IM>
__global__ void gemm_tc(const float* __restrict__ A, const float* __restrict__ Bm,
                        float* __restrict__ C, int M, int N, int K,
                        long long sA, long long sB, long long sC) {
    constexpr int TM = 32 * IM;
    A  += (long long)blockIdx.z * sA;
    Bm += (long long)blockIdx.z * sB;
    C  += (long long)blockIdx.z * sC;

    __shared__ alignas(16) __nv_bfloat16 Ah[TM][40], Al[TM][40];  // 80B rows
    __shared__ alignas(16) __nv_bfloat16 Bh[32][72], Bl[32][72];  // 144B rows

    const int tid  = threadIdx.x;
    const int lane = tid & 31;
    const int warp = tid >> 5;
    const int wm   = warp >> 2;           // 0..1
    const int wn   = warp & 3;            // 0..3
    const int gid  = lane >> 2;           // 0..7 (mma d-frag row)
    const int tig  = lane & 3;            // 0..3 (mma d-frag col pair)
    const int m_base = wm * (16 * IM);
    const int n_base = wn * 16;
    const int m0 = blockIdx.y * TM;
    const int n0 = blockIdx.x * 64;

    // ldmatrix lane -> (row, col) address components (tile = lane>>3)
    const int l8   = lane & 7;
    const int t8   = lane >> 3;
    const int rrow = l8 + ((t8 & 1) << 3);   // +8 rows for tiles 1,3
    const int rcol = (t8 >> 1) << 3;         // +8 halves for tiles 2,3

    const unsigned baseAh = smem_u32(&Ah[0][0]);
    const unsigned baseAl = smem_u32(&Al[0][0]);
    const unsigned baseBh = smem_u32(&Bh[0][0]);
    const unsigned baseBl = smem_u32(&Bl[0][0]);

    float acc[IM][2][4];
#pragma unroll
    for (int im = 0; im < IM; im++)
#pragma unroll
        for (int in = 0; in < 2; in++)
#pragma unroll
            for (int c = 0; c < 4; c++) acc[im][in][c] = 0.0f;

    for (int k0 = 0; k0 < K; k0 += 32) {
        // A tile (TM x 32): IM float4 per thread, hi/lo bf16 split
#pragma unroll
        for (int it = 0; it < IM; it++) {
            int idx = tid + it * 256;
            int r = idx >> 3;
            int c = (idx & 7) << 2;
            float4 v = *(const float4*)&A[(long long)(m0 + r) * K + k0 + c];
            split_store8(v, &Ah[r][c], &Al[r][c]);
        }
        // B tile (32 x 64): 2 float4 per thread
#pragma unroll
        for (int it = 0; it < 2; it++) {
            int idx = tid + it * 256;
            int r = idx >> 4;
            int c = (idx & 15) << 2;
            float4 v = *(const float4*)&Bm[(long long)(k0 + r) * N + n0 + c];
            split_store8(v, &Bh[r][c], &Bl[r][c]);
        }
        __syncthreads();

#pragma unroll
        for (int kk = 0; kk < 2; kk++) {
            const int kb = kk << 4;
            unsigned ah[IM][4], al[IM][4], bh[4], bl[4];
#pragma unroll
            for (int im = 0; im < IM; im++) {
                unsigned ra = ((unsigned)((m_base + 16 * im + rrow) * 40 + kb + rcol)) << 1;
                ldsm_x4(ah[im], baseAh + ra);
                ldsm_x4(al[im], baseAl + ra);
            }
            unsigned rb = ((unsigned)((kb + rrow) * 72 + n_base + rcol)) << 1;
            ldsm_x4_t(bh, baseBh + rb);
            ldsm_x4_t(bl, baseBl + rb);

#pragma unroll
            for (int im = 0; im < IM; im++) {
                // n-block 0 uses (bh[0],bh[1]) / (bl[0],bl[1]); n-block 1 the 2/3 pair
                mma_bf16(acc[im][0], ah[im], bh[0], bh[1]);
                mma_bf16(acc[im][0], ah[im], bl[0], bl[1]);
                mma_bf16(acc[im][0], al[im], bh[0], bh[1]);
                mma_bf16(acc[im][1], ah[im], bh[2], bh[3]);
                mma_bf16(acc[im][1], ah[im], bl[2], bl[3]);
                mma_bf16(acc[im][1], al[im], bh[2], bh[3]);
            }
        }
        __syncthreads();
    }

#pragma unroll
    for (int im = 0; im < IM; im++) {
#pragma unroll
        for (int in = 0; in < 2; in++) {
            int row = m0 + m_base + 16 * im + gid;
            int col = n0 + n_base + 8 * in + 2 * tig;
            float* d = acc[im][in];
            *(float2*)&C[(long long)row * N + col]       = make_float2(d[0], d[1]);
            *(float2*)&C[(long long)(row + 8) * N + col] = make_float2(d[2], d[3]);
        }
    }
}

// ---------------------------------------------------------------------------
// Scores (R6 version, at its MUFU floor): j-column per thread, k in registers
// (double-buffered), q via broadcast LDS. tanh.approx.f32 (rt8).
// score[b,i,j] = sum_u tanh(q[b,i,u] + k[b,j,u]) * wv[u]
// ---------------------------------------------------------------------------
#define TQ 16

__global__ void scores_kernel(const float* __restrict__ wv, float* __restrict__ attn) {
    const int b  = blockIdx.z;
    const int ib = blockIdx.y;
    const int tid = threadIdx.x;
    const int j  = blockIdx.x * 256 + tid;

    __shared__ float qs[TQ][U_];   // 16 KB
    __shared__ float wvs[U_];

    const float* qbase = g_q + ((long long)(b * SQ_ + ib * TQ)) * U_;
#pragma unroll
    for (int l = 0; l < 4; l++) {
        int idx = tid + l * 256;
        int row = idx >> 6;
        int col = (idx & 63) << 2;
        *(float4*)&qs[row][col] = *(const float4*)&qbase[(long long)row * U_ + col];
    }
    if (tid < 64) *(float4*)&wvs[tid << 2] = *(const float4*)&wv[tid << 2];
    __syncthreads();

    const float* kp = g_k + ((long long)(b * SK_) + j) * U_;

    float acc[TQ];
#pragma unroll
    for (int i = 0; i < TQ; i++) acc[i] = 0.0f;

    float4 ka = *(const float4*)&kp[0];
    float4 kb = *(const float4*)&kp[4];

    for (int uc = 0; uc < U_; uc += 8) {
        int un = (uc + 8 < U_) ? uc + 8 : uc;   // clamped tail prefetch
        float4 kna = *(const float4*)&kp[un];
        float4 knb = *(const float4*)&kp[un + 4];
        float4 w0 = *(const float4*)&wvs[uc];
        float4 w1 = *(const float4*)&wvs[uc + 4];
#pragma unroll
        for (int i = 0; i < TQ; i++) {
            float4 q0 = *(const float4*)&qs[i][uc];        // broadcast LDS
            float4 q1 = *(const float4*)&qs[i][uc + 4];    // broadcast LDS
            float s;
            s  = tanha(q0.x + ka.x) * w0.x;
            s += tanha(q0.y + ka.y) * w0.y;
            s += tanha(q0.z + ka.z) * w0.z;
            s += tanha(q0.w + ka.w) * w0.w;
            s += tanha(q1.x + kb.x) * w1.x;
            s += tanha(q1.y + kb.y) * w1.y;
            s += tanha(q1.z + kb.z) * w1.z;
            s += tanha(q1.w + kb.w) * w1.w;
            acc[i] += s;
        }
        ka = kna;
        kb = knb;
    }

    long long base = ((long long)(b * SQ_ + ib * TQ)) * SK_ + j;
#pragma unroll
    for (int i = 0; i < TQ; i++) attn[base + (long long)i * SK_] = acc[i];
}

// ---------------------------------------------------------------------------
// Row softmax over SK=1024, in place. One CTA (256 threads) per (b,i) row.
// ---------------------------------------------------------------------------
__global__ void softmax_kernel(float* __restrict__ attn) {
    float* p = attn + (long long)blockIdx.x * SK_;
    const int tid = threadIdx.x;
    __shared__ float red[8];

    float4 x = *(const float4*)&p[tid << 2];
    float m = fmaxf(fmaxf(x.x, x.y), fmaxf(x.z, x.w));
#pragma unroll
    for (int o = 16; o; o >>= 1) m = fmaxf(m, __shfl_xor_sync(0xffffffffu, m, o));
    if ((tid & 31) == 0) red[tid >> 5] = m;
    __syncthreads();
    float M = red[0];
#pragma unroll
    for (int w = 1; w < 8; w++) M = fmaxf(M, red[w]);

    float4 e;
    e.x = __expf(x.x - M);
    e.y = __expf(x.y - M);
    e.z = __expf(x.z - M);
    e.w = __expf(x.w - M);
    float s = (e.x + e.y) + (e.z + e.w);
#pragma unroll
    for (int o = 16; o; o >>= 1) s += __shfl_xor_sync(0xffffffffu, s, o);
    __syncthreads();
    if ((tid & 31) == 0) red[tid >> 5] = s;
    __syncthreads();
    float S = 0.f;
#pragma unroll
    for (int w = 0; w < 8; w++) S += red[w];
    float inv = 1.0f / S;
    e.x *= inv; e.y *= inv; e.z *= inv; e.w *= inv;
    *(float4*)&p[tid << 2] = e;
}

// ---------------------------------------------------------------------------
extern "C" void kernel_launch(void* const* d_in, const int* in_sizes, int n_in,
                              void* d_out, int out_size) {
    const float* query = (const float*)d_in[0];
    const float* key   = (const float*)d_in[1];
    const float* value = (const float*)d_in[2];
    const float* Wq    = (const float*)d_in[3];
    const float* Wk    = (const float*)d_in[4];
    const float* wv    = (const float*)d_in[5];

    float* out  = (float*)d_out;
    float* ctx  = out;                            // [B, SQ, U]
    float* attn = out + (long long)B_ * SQ_ * U_; // [B, SQ, SK]

    void* pq = nullptr; void* pk = nullptr;
    cudaGetSymbolAddress(&pq, g_q);
    cudaGetSymbolAddress(&pk, g_k);
    float* dq = (float*)pq;
    float* dk = (float*)pk;

    // 1) Projections on tensor cores (bf16 3-term split)
    gemm_tc<2><<<dim3(U_ / 64, (B_ * SQ_) / 64, 1), 256>>>(
        query, Wq, dq, B_ * SQ_, U_, U_, 0, 0, 0);
    gemm_tc<2><<<dim3(U_ / 64, (B_ * SK_) / 64, 1), 256>>>(
        key, Wk, dk, B_ * SK_, U_, U_, 0, 0, 0);

    // 2) Raw scores into the attention-weights output region
    scores_kernel<<<dim3(SK_ / 256, SQ_ / TQ, B_), 256>>>(wv, attn);

    // 3) Softmax in place
    softmax_kernel<<<B_ * SQ_, 256>>>(attn);

    // 4) context = attn @ value (batched, M=128 N=256 K=1024)
    gemm_tc<1><<<dim3(U_ / 64, SQ_ / 32, B_), 256>>>(
        attn, value, ctx, SQ_, U_, SK_,
        (long long)SQ_ * SK_, (long long)SK_ * U_, (long long)SQ_ * U_);
}

// round 11
// speedup vs baseline: 1.7164x; 1.0505x over previous
#include <cuda_runtime.h>
#include <cuda_bf16.h>
#include <math_constants.h>

#define B_  8
#define SQ_ 128
#define SK_ 1024
#define U_  256

// Scratch: projections in MIXED layout (u%4 in {0,1}: raw, {2,3}: tanh'd)
__device__ float g_q[B_ * SQ_ * U_];   // 1 MB
__device__ float g_k[B_ * SK_ * U_];   // 8 MB

__device__ __forceinline__ float tanha(float x) {
    float y;
    asm("tanh.approx.f32 %0, %1;" : "=f"(y) : "f"(x));
    return y;
}

// Division-free reciprocal: magic-constant seed (ALU) + 2 Newton (FMA pipe).
// No MUFU. Rel err ~1.3e-5 after 2 iterations. Safe for den in [0, 2].
__device__ __forceinline__ float rcp_fma(float den) {
    float y = __uint_as_float(0x7EF311C3u - __float_as_uint(den));
    y = y * (2.0f - den * y);
    y = y * (2.0f - den * y);
    return y;
}

__device__ __forceinline__ unsigned smem_u32(const void* p) {
    return (unsigned)__cvta_generic_to_shared(p);
}

// ---------------------------------------------------------------------------
// bf16 3-term split GEMM helpers
// ---------------------------------------------------------------------------
__device__ __forceinline__ void split_store8(float4 v,
                                             __nv_bfloat16* ph, __nv_bfloat16* pl) {
    __nv_bfloat162 h01 = __floats2bfloat162_rn(v.x, v.y);
    __nv_bfloat162 h23 = __floats2bfloat162_rn(v.z, v.w);
    __nv_bfloat162 l01 = __floats2bfloat162_rn(v.x - __bfloat162float(h01.x),
                                               v.y - __bfloat162float(h01.y));
    __nv_bfloat162 l23 = __floats2bfloat162_rn(v.z - __bfloat162float(h23.x),
                                               v.w - __bfloat162float(h23.y));
    *reinterpret_cast<__nv_bfloat162*>(ph)     = h01;
    *reinterpret_cast<__nv_bfloat162*>(ph + 2) = h23;
    *reinterpret_cast<__nv_bfloat162*>(pl)     = l01;
    *reinterpret_cast<__nv_bfloat162*>(pl + 2) = l23;
}

__device__ __forceinline__ void ldsm_x4(unsigned r[4], unsigned addr) {
    asm volatile("ldmatrix.sync.aligned.m8n8.x4.shared.b16 {%0,%1,%2,%3}, [%4];"
        : "=r"(r[0]), "=r"(r[1]), "=r"(r[2]), "=r"(r[3]) : "r"(addr));
}

__device__ __forceinline__ void ldsm_x4_t(unsigned r[4], unsigned addr) {
    asm volatile("ldmatrix.sync.aligned.m8n8.x4.trans.shared.b16 {%0,%1,%2,%3}, [%4];"
        : "=r"(r[0]), "=r"(r[1]), "=r"(r[2]), "=r"(r[3]) : "r"(addr));
}

__device__ __forceinline__ void mma_bf16(float* d, const unsigned a[4],
                                         unsigned b0, unsigned b1) {
    asm volatile("mma.sync.aligned.m16n8k16.row.col.f32.bf16.bf16.f32 "
        "{%0,%1,%2,%3}, {%4,%5,%6,%7}, {%8,%9}, {%0,%1,%2,%3};"
        : "+f"(d[0]), "+f"(d[1]), "+f"(d[2]), "+f"(d[3])
        : "r"(a[0]), "r"(a[1]), "r"(a[2]), "r"(a[3]), "r"(b0), "r"(b1));
}

// ---------------------------------------------------------------------------
// Tensor-core SGEMM, bf16 3-term split: C = A @ B (row-major f32 in/out).
// CTA tile: (32*IM) x 64, K-chunk 32. 8 warps 2(m) x 4(n), ldmatrix frags.
// MIXEPI=1: epilogue writes raw on cols%4 in {0,1}, tanh'd on {2,3}
// (selected by tig&1), producing the mixed layout the scores kernel needs.
// ---------------------------------------------------------------------------
template <int IM, int MIXEPI>
__global__ void gemm_tc(const float* __restrict__ A, const float* __restrict__ Bm,
                        float* __restrict__ C, int M, int N, int K,
                        long long sA, long long sB, long long sC) {
    constexpr int TM = 32 * IM;
    A  += (long long)blockIdx.z * sA;
    Bm += (long long)blockIdx.z * sB;
    C  += (long long)blockIdx.z * sC;

    __shared__ alignas(16) __nv_bfloat16 Ah[TM][40], Al[TM][40];
    __shared__ alignas(16) __nv_bfloat16 Bh[32][72], Bl[32][72];

    const int tid  = threadIdx.x;
    const int lane = tid & 31;
    const int warp = tid >> 5;
    const int wm   = warp >> 2;
    const int wn   = warp & 3;
    const int gid  = lane >> 2;
    const int tig  = lane & 3;
    const int m_base = wm * (16 * IM);
    const int n_base = wn * 16;
    const int m0 = blockIdx.y * TM;
    const int n0 = blockIdx.x * 64;

    const int l8   = lane & 7;
    const int t8   = lane >> 3;
    const int rrow = l8 + ((t8 & 1) << 3);
    const int rcol = (t8 >> 1) << 3;

    const unsigned baseAh = smem_u32(&Ah[0][0]);
    const unsigned baseAl = smem_u32(&Al[0][0]);
    const unsigned baseBh = smem_u32(&Bh[0][0]);
    const unsigned baseBl = smem_u32(&Bl[0][0]);

    float acc[IM][2][4];
#pragma unroll
    for (int im = 0; im < IM; im++)
#pragma unroll
        for (int in = 0; in < 2; in++)
#pragma unroll
            for (int c = 0; c < 4; c++) acc[im][in][c] = 0.0f;

    for (int k0 = 0; k0 < K; k0 += 32) {
#pragma unroll
        for (int it = 0; it < IM; it++) {
            int idx = tid + it * 256;
            int r = idx >> 3;
            int c = (idx & 7) << 2;
            float4 v = *(const float4*)&A[(long long)(m0 + r) * K + k0 + c];
            split_store8(v, &Ah[r][c], &Al[r][c]);
        }
#pragma unroll
        for (int it = 0; it < 2; it++) {
            int idx = tid + it * 256;
            int r = idx >> 4;
            int c = (idx & 15) << 2;
            float4 v = *(const float4*)&Bm[(long long)(k0 + r) * N + n0 + c];
            split_store8(v, &Bh[r][c], &Bl[r][c]);
        }
        __syncthreads();

#pragma unroll
        for (int kk = 0; kk < 2; kk++) {
            const int kb = kk << 4;
            unsigned ah[IM][4], al[IM][4], bh[4], bl[4];
#pragma unroll
            for (int im = 0; im < IM; im++) {
                unsigned ra = ((unsigned)((m_base + 16 * im + rrow) * 40 + kb + rcol)) << 1;
                ldsm_x4(ah[im], baseAh + ra);
                ldsm_x4(al[im], baseAl + ra);
            }
            unsigned rb = ((unsigned)((kb + rrow) * 72 + n_base + rcol)) << 1;
            ldsm_x4_t(bh, baseBh + rb);
            ldsm_x4_t(bl, baseBl + rb);

#pragma unroll
            for (int im = 0; im < IM; im++) {
                mma_bf16(acc[im][0], ah[im], bh[0], bh[1]);
                mma_bf16(acc[im][0], ah[im], bl[0], bl[1]);
                mma_bf16(acc[im][0], al[im], bh[0], bh[1]);
                mma_bf16(acc[im][1], ah[im], bh[2], bh[3]);
                mma_bf16(acc[im][1], ah[im], bl[2], bl[3]);
                mma_bf16(acc[im][1], al[im], bh[2], bh[3]);
            }
        }
        __syncthreads();
    }

    const bool dotanh = MIXEPI && (tig & 1);
#pragma unroll
    for (int im = 0; im < IM; im++) {
#pragma unroll
        for (int in = 0; in < 2; in++) {
            int row = m0 + m_base + 16 * im + gid;
            int col = n0 + n_base + 8 * in + 2 * tig;
            float* d = acc[im][in];
            if (dotanh) {
#pragma unroll
                for (int c = 0; c < 4; c++) d[c] = tanha(d[c]);
            }
            *(float2*)&C[(long long)row * N + col]       = make_float2(d[0], d[1]);
            *(float2*)&C[(long long)(row + 8) * N + col] = make_float2(d[2], d[3]);
        }
    }
}

// ---------------------------------------------------------------------------
// Scores v6 (pipe-split tanh): components x,y of each float4 are RAW q/k ->
// MUFU tanh(q+k). Components z,w are PRE-TANH'D (projection epilogue) ->
// exact identity tanh(q+k) = (tq+tk)/(1+tq*tk) with division-free Newton
// rcp on the FMA/ALU pipes. MUFU load halved: floor 226k -> ~141k cyc/SM.
// ---------------------------------------------------------------------------
#define TQ 16

__global__ void scores_kernel(const float* __restrict__ wv, float* __restrict__ attn) {
    const int b  = blockIdx.z;
    const int ib = blockIdx.y;
    const int tid = threadIdx.x;
    const int j  = blockIdx.x * 256 + tid;

    __shared__ float qs[TQ][U_];   // 16 KB (mixed layout)
    __shared__ float wvs[U_];

    const float* qbase = g_q + ((long long)(b * SQ_ + ib * TQ)) * U_;
#pragma unroll
    for (int l = 0; l < 4; l++) {
        int idx = tid + l * 256;
        int row = idx >> 6;
        int col = (idx & 63) << 2;
        *(float4*)&qs[row][col] = *(const float4*)&qbase[(long long)row * U_ + col];
    }
    if (tid < 64) *(float4*)&wvs[tid << 2] = *(const float4*)&wv[tid << 2];
    __syncthreads();

    const float* kp = g_k + ((long long)(b * SK_) + j) * U_;

    float acc[TQ];
#pragma unroll
    for (int i = 0; i < TQ; i++) acc[i] = 0.0f;

    float4 ka = *(const float4*)&kp[0];
    float4 kb = *(const float4*)&kp[4];

    for (int uc = 0; uc < U_; uc += 8) {
        int un = (uc + 8 < U_) ? uc + 8 : uc;   // clamped tail prefetch
        float4 kna = *(const float4*)&kp[un];
        float4 knb = *(const float4*)&kp[un + 4];
        float4 w0 = *(const float4*)&wvs[uc];
        float4 w1 = *(const float4*)&wvs[uc + 4];
#pragma unroll
        for (int i = 0; i < TQ; i++) {
            float4 q0 = *(const float4*)&qs[i][uc];        // broadcast LDS
            float4 q1 = *(const float4*)&qs[i][uc + 4];
            float a = acc[i];
            // MUFU path (raw components x, y)
            a = fmaf(tanha(q0.x + ka.x), w0.x, a);
            a = fmaf(tanha(q0.y + ka.y), w0.y, a);
            a = fmaf(tanha(q1.x + kb.x), w1.x, a);
            a = fmaf(tanha(q1.y + kb.y), w1.y, a);
            // FMA path (pre-tanh'd components z, w): exact addition identity
            {
                float nm = q0.z + ka.z;
                float r  = rcp_fma(fmaf(q0.z, ka.z, 1.0f));
                a = fmaf(nm * r, w0.z, a);
            }
            {
                float nm = q0.w + ka.w;
                float r  = rcp_fma(fmaf(q0.w, ka.w, 1.0f));
                a = fmaf(nm * r, w0.w, a);
            }
            {
                float nm = q1.z + kb.z;
                float r  = rcp_fma(fmaf(q1.z, kb.z, 1.0f));
                a = fmaf(nm * r, w1.z, a);
            }
            {
                float nm = q1.w + kb.w;
                float r  = rcp_fma(fmaf(q1.w, kb.w, 1.0f));
                a = fmaf(nm * r, w1.w, a);
            }
            acc[i] = a;
        }
        ka = kna;
        kb = knb;
    }

    long long base = ((long long)(b * SQ_ + ib * TQ)) * SK_ + j;
#pragma unroll
    for (int i = 0; i < TQ; i++) attn[base + (long long)i * SK_] = acc[i];
}

// ---------------------------------------------------------------------------
// Row softmax over SK=1024, in place. One CTA (256 threads) per (b,i) row.
// ---------------------------------------------------------------------------
__global__ void softmax_kernel(float* __restrict__ attn) {
    float* p = attn + (long long)blockIdx.x * SK_;
    const int tid = threadIdx.x;
    __shared__ float red[8];

    float4 x = *(const float4*)&p[tid << 2];
    float m = fmaxf(fmaxf(x.x, x.y), fmaxf(x.z, x.w));
#pragma unroll
    for (int o = 16; o; o >>= 1) m = fmaxf(m, __shfl_xor_sync(0xffffffffu, m, o));
    if ((tid & 31) == 0) red[tid >> 5] = m;
    __syncthreads();
    float M = red[0];
#pragma unroll
    for (int w = 1; w < 8; w++) M = fmaxf(M, red[w]);

    float4 e;
    e.x = __expf(x.x - M);
    e.y = __expf(x.y - M);
    e.z = __expf(x.z - M);
    e.w = __expf(x.w - M);
    float s = (e.x + e.y) + (e.z + e.w);
#pragma unroll
    for (int o = 16; o; o >>= 1) s += __shfl_xor_sync(0xffffffffu, s, o);
    __syncthreads();
    if ((tid & 31) == 0) red[tid >> 5] = s;
    __syncthreads();
    float S = 0.f;
#pragma unroll
    for (int w = 0; w < 8; w++) S += red[w];
    float inv = 1.0f / S;
    e.x *= inv; e.y *= inv; e.z *= inv; e.w *= inv;
    *(float4*)&p[tid << 2] = e;
}

// ---------------------------------------------------------------------------
extern "C" void kernel_launch(void* const* d_in, const int* in_sizes, int n_in,
                              void* d_out, int out_size) {
    const float* query = (const float*)d_in[0];
    const float* key   = (const float*)d_in[1];
    const float* value = (const float*)d_in[2];
    const float* Wq    = (const float*)d_in[3];
    const float* Wk    = (const float*)d_in[4];
    const float* wv    = (const float*)d_in[5];

    float* out  = (float*)d_out;
    float* ctx  = out;                            // [B, SQ, U]
    float* attn = out + (long long)B_ * SQ_ * U_; // [B, SQ, SK]

    void* pq = nullptr; void* pk = nullptr;
    cudaGetSymbolAddress(&pq, g_q);
    cudaGetSymbolAddress(&pk, g_k);
    float* dq = (float*)pq;
    float* dk = (float*)pk;

    // 1) Projections on tensor cores, MIXED epilogue (raw / tanh'd by u%4)
    gemm_tc<2, 1><<<dim3(U_ / 64, (B_ * SQ_) / 64, 1), 256>>>(
        query, Wq, dq, B_ * SQ_, U_, U_, 0, 0, 0);
    gemm_tc<2, 1><<<dim3(U_ / 64, (B_ * SK_) / 64, 1), 256>>>(
        key, Wk, dk, B_ * SK_, U_, U_, 0, 0, 0);

    // 2) Raw scores (pipe-split tanh) into the attention-weights region
    scores_kernel<<<dim3(SK_ / 256, SQ_ / TQ, B_), 256>>>(wv, attn);

    // 3) Softmax in place
    softmax_kernel<<<B_ * SQ_, 256>>>(attn);

    // 4) context = attn @ value (batched, plain epilogue)
    gemm_tc<1, 0><<<dim3(U_ / 64, SQ_ / 32, B_), 256>>>(
        attn, value, ctx, SQ_, U_, SK_,
        (long long)SQ_ * SK_, (long long)SK_ * U_, (long long)SQ_ * U_);
}